// round 2
// baseline (speedup 1.0000x reference)
#include <cuda_runtime.h>

// Problem constants
#define BB 4
#define QQ 256
#define MMM 256
#define HH 512
#define DQS 512
#define DKS 512
#define DC (DQS + DKS)

// Scratch (device globals — no allocation allowed)
__device__ float g_qproj[BB * QQ * HH];   // 2 MB
__device__ float g_kproj[BB * MMM * HH];  // 2 MB
__device__ float g_comb[BB * QQ * DC];    // 4 MB  [row][0:512)=query, [512:1024)=attns

// ---------------------------------------------------------------------------
// Copy query into first half of combined buffer (float4 copy)
// ---------------------------------------------------------------------------
__global__ void copy_query_kernel(const float* __restrict__ q) {
    int i4 = blockIdx.x * blockDim.x + threadIdx.x;
    if (i4 >= BB * QQ * DQS / 4) return;
    int row = i4 >> 7;        // 128 float4 per 512-float row
    int c4 = i4 & 127;
    reinterpret_cast<float4*>(g_comb)[row * (DC / 4) + c4] =
        reinterpret_cast<const float4*>(q)[i4];
}

// ---------------------------------------------------------------------------
// Generic NT SGEMM:  C[r][n] = act( sum_k A[r*lda+k] * W[n*ldw+k] + bias[n] )
// 64x64 tile, 128 threads, 8x4 micro-tile, register double-buffered loads.
// Requires: rows % 64 == 0, N % 64 == 0, K % 16 == 0, lda/ldw mult of 4.
// ---------------------------------------------------------------------------
__global__ void __launch_bounds__(128) gemm_nt(
    const float* __restrict__ A, int lda,
    const float* __restrict__ W, int ldw,
    const float* __restrict__ bias,
    float* __restrict__ C, int ldc,
    int K, int doTanh)
{
    __shared__ float As[16][64];
    __shared__ float Ws[16][64];

    const int tid = threadIdx.x;
    const int tx = tid & 15;          // col group (4 cols)
    const int ty = tid >> 4;          // row group (8 rows)
    const int row0 = blockIdx.y << 6;
    const int col0 = blockIdx.x << 6;

    // loader indices: 256 float4 per tile, 2 per thread
    const int idx0 = tid;
    const int idx1 = tid + 128;
    const int r0 = idx0 >> 2, kq0 = (idx0 & 3) << 2;
    const int r1 = idx1 >> 2, kq1 = (idx1 & 3) << 2;

    float acc[8][4];
#pragma unroll
    for (int i = 0; i < 8; i++)
#pragma unroll
        for (int j = 0; j < 4; j++) acc[i][j] = 0.f;

    // initial prefetch (k0 = 0)
    float4 pa0 = *reinterpret_cast<const float4*>(A + (size_t)(row0 + r0) * lda + kq0);
    float4 pa1 = *reinterpret_cast<const float4*>(A + (size_t)(row0 + r1) * lda + kq1);
    float4 pw0 = *reinterpret_cast<const float4*>(W + (size_t)(col0 + r0) * ldw + kq0);
    float4 pw1 = *reinterpret_cast<const float4*>(W + (size_t)(col0 + r1) * ldw + kq1);

    for (int k0 = 0; k0 < K; k0 += 16) {
        // store prefetched tile to smem
        As[kq0 + 0][r0] = pa0.x; As[kq0 + 1][r0] = pa0.y;
        As[kq0 + 2][r0] = pa0.z; As[kq0 + 3][r0] = pa0.w;
        As[kq1 + 0][r1] = pa1.x; As[kq1 + 1][r1] = pa1.y;
        As[kq1 + 2][r1] = pa1.z; As[kq1 + 3][r1] = pa1.w;
        Ws[kq0 + 0][r0] = pw0.x; Ws[kq0 + 1][r0] = pw0.y;
        Ws[kq0 + 2][r0] = pw0.z; Ws[kq0 + 3][r0] = pw0.w;
        Ws[kq1 + 0][r1] = pw1.x; Ws[kq1 + 1][r1] = pw1.y;
        Ws[kq1 + 2][r1] = pw1.z; Ws[kq1 + 3][r1] = pw1.w;
        __syncthreads();

        // prefetch next k-tile while computing on current
        int kn = k0 + 16;
        if (kn < K) {
            pa0 = *reinterpret_cast<const float4*>(A + (size_t)(row0 + r0) * lda + kn + kq0);
            pa1 = *reinterpret_cast<const float4*>(A + (size_t)(row0 + r1) * lda + kn + kq1);
            pw0 = *reinterpret_cast<const float4*>(W + (size_t)(col0 + r0) * ldw + kn + kq0);
            pw1 = *reinterpret_cast<const float4*>(W + (size_t)(col0 + r1) * ldw + kn + kq1);
        }

#pragma unroll
        for (int k = 0; k < 16; k++) {
            float4 a0 = *reinterpret_cast<const float4*>(&As[k][ty << 3]);
            float4 a1 = *reinterpret_cast<const float4*>(&As[k][(ty << 3) + 4]);
            float4 w  = *reinterpret_cast<const float4*>(&Ws[k][tx << 2]);
            float ar[8] = {a0.x, a0.y, a0.z, a0.w, a1.x, a1.y, a1.z, a1.w};
            float wr[4] = {w.x, w.y, w.z, w.w};
#pragma unroll
            for (int i = 0; i < 8; i++)
#pragma unroll
                for (int j = 0; j < 4; j++)
                    acc[i][j] = fmaf(ar[i], wr[j], acc[i][j]);
        }
        __syncthreads();
    }

    float bv[4];
#pragma unroll
    for (int j = 0; j < 4; j++)
        bv[j] = bias ? bias[col0 + (tx << 2) + j] : 0.f;

#pragma unroll
    for (int i = 0; i < 8; i++) {
        float4 o;
        float* op = &o.x;
#pragma unroll
        for (int j = 0; j < 4; j++) {
            float c = acc[i][j] + bv[j];
            if (doTanh) c = tanhf(c);
            op[j] = c;
        }
        *reinterpret_cast<float4*>(
            C + (size_t)(row0 + (ty << 3) + i) * ldc + col0 + (tx << 2)) = o;
    }
}

// ---------------------------------------------------------------------------
// Scores + softmax kernel (the hot one — MUFU tanh bound).
// 256 blocks (b, 4 q-rows), 128 threads = 4 warps, 1 warp per q-row.
// q-row and Wl live lane-strided in registers; k staged in 16-row smem tiles.
// mask is read as 4-byte elements (bool widened to int32 or float32 by the
// harness); "masked" == any nonzero bit pattern (covers both 1 and 1.0f).
// ---------------------------------------------------------------------------
__global__ void __launch_bounds__(128) scores_kernel(
    const float* __restrict__ Wl,
    const float* __restrict__ blp,
    const unsigned int* __restrict__ mask,   // [B, M] 4-byte bool
    float* __restrict__ weights)             // [B, Q, M]
{
    const int bx = blockIdx.x;       // 0..255
    const int b  = bx >> 6;          // 64 blocks per batch
    const int q0 = (bx & 63) << 2;
    const int tid  = threadIdx.x;
    const int lane = tid & 31;
    const int w    = tid >> 5;       // warp id = local q row
    const int q    = q0 + w;

    __shared__ float ks[16][512];          // 32 KB k tile
    __shared__ float sc[4][256];           // per-warp scores
    __shared__ unsigned char mk[256];

    mk[tid]       = (mask[b * MMM + tid] != 0u);
    mk[tid + 128] = (mask[b * MMM + tid + 128] != 0u);

    // register-resident q row and Wl (lane-strided -> coalesced)
    float qr[16], wl[16];
    const float* qp = g_qproj + ((size_t)(b * QQ + q)) * HH;
#pragma unroll
    for (int j = 0; j < 16; j++) {
        qr[j] = qp[lane + 32 * j];
        wl[j] = Wl[lane + 32 * j];
    }

    for (int m0 = 0; m0 < MMM; m0 += 16) {
        __syncthreads();
        // load 16x512 k tile (2048 float4 / 128 threads = 16 each)
        const float* kp = g_kproj + ((size_t)(b * MMM + m0)) * HH;
#pragma unroll
        for (int i = 0; i < 16; i++) {
            int idx = tid + (i << 7);
            int mm  = idx >> 7;
            int c4  = (idx & 127) << 2;
            *reinterpret_cast<float4*>(&ks[mm][c4]) =
                *reinterpret_cast<const float4*>(kp + mm * HH + c4);
        }
        __syncthreads();

#pragma unroll 4
        for (int mm = 0; mm < 16; mm++) {
            float acc = 0.f;
#pragma unroll
            for (int j = 0; j < 16; j++) {
                float s = qr[j] + ks[mm][lane + 32 * j];
                float t;
                asm("tanh.approx.f32 %0, %1;" : "=f"(t) : "f"(s));
                acc = fmaf(wl[j], t, acc);
            }
#pragma unroll
            for (int o = 16; o > 0; o >>= 1)
                acc += __shfl_xor_sync(0xFFFFFFFFu, acc, o);
            if (lane == 0) sc[w][m0 + mm] = acc;
        }
    }
    __syncthreads();

    // per-warp softmax over 256 scores
    const float bl = blp[0];
    float v[8];
    float mx = -3.4e38f;
#pragma unroll
    for (int j = 0; j < 8; j++) {
        int m = lane + 32 * j;
        float s = sc[w][m] + bl;
        if (mk[m]) s = -1e18f;
        v[j] = s;
        mx = fmaxf(mx, s);
    }
#pragma unroll
    for (int o = 16; o > 0; o >>= 1)
        mx = fmaxf(mx, __shfl_xor_sync(0xFFFFFFFFu, mx, o));
    float sum = 0.f;
#pragma unroll
    for (int j = 0; j < 8; j++) {
        v[j] = __expf(v[j] - mx);
        sum += v[j];
    }
#pragma unroll
    for (int o = 16; o > 0; o >>= 1)
        sum += __shfl_xor_sync(0xFFFFFFFFu, sum, o);
    float inv = 1.f / sum;

    float* wout = weights + ((size_t)(b * QQ + q)) * MMM;
#pragma unroll
    for (int j = 0; j < 8; j++)
        wout[lane + 32 * j] = v[j] * inv;
}

// ---------------------------------------------------------------------------
// attns = weights @ memory  (batched NN GEMM), writes into g_comb[:,512:1024]
// 64x64 tile over (q, d), K = M = 256. grid (8, 4, B), 128 threads.
// ---------------------------------------------------------------------------
__global__ void __launch_bounds__(128) attn_gemm(
    const float* __restrict__ Wt,    // weights [B,Q,M]
    const float* __restrict__ mem)   // memory  [B,M,KS]
{
    const int b = blockIdx.z;
    const float* A  = Wt  + (size_t)b * QQ * MMM;   // lda = M
    const float* Bm = mem + (size_t)b * MMM * DKS;  // ldb = KS

    __shared__ float As[16][64];
    __shared__ float Bs[16][64];

    const int tid = threadIdx.x;
    const int tx = tid & 15;
    const int ty = tid >> 4;
    const int row0 = blockIdx.y << 6;   // q
    const int col0 = blockIdx.x << 6;   // d

    const int idx0 = tid, idx1 = tid + 128;
    const int ar0 = idx0 >> 2, akq0 = (idx0 & 3) << 2;
    const int ar1 = idx1 >> 2, akq1 = (idx1 & 3) << 2;
    const int bk0 = idx0 >> 4, bn0 = (idx0 & 15) << 2;
    const int bk1 = idx1 >> 4, bn1 = (idx1 & 15) << 2;

    float acc[8][4];
#pragma unroll
    for (int i = 0; i < 8; i++)
#pragma unroll
        for (int j = 0; j < 4; j++) acc[i][j] = 0.f;

    for (int k0 = 0; k0 < MMM; k0 += 16) {
        float4 a0 = *reinterpret_cast<const float4*>(A + (size_t)(row0 + ar0) * MMM + k0 + akq0);
        float4 a1 = *reinterpret_cast<const float4*>(A + (size_t)(row0 + ar1) * MMM + k0 + akq1);
        float4 b0 = *reinterpret_cast<const float4*>(Bm + (size_t)(k0 + bk0) * DKS + col0 + bn0);
        float4 b1 = *reinterpret_cast<const float4*>(Bm + (size_t)(k0 + bk1) * DKS + col0 + bn1);
        As[akq0 + 0][ar0] = a0.x; As[akq0 + 1][ar0] = a0.y;
        As[akq0 + 2][ar0] = a0.z; As[akq0 + 3][ar0] = a0.w;
        As[akq1 + 0][ar1] = a1.x; As[akq1 + 1][ar1] = a1.y;
        As[akq1 + 2][ar1] = a1.z; As[akq1 + 3][ar1] = a1.w;
        *reinterpret_cast<float4*>(&Bs[bk0][bn0]) = b0;
        *reinterpret_cast<float4*>(&Bs[bk1][bn1]) = b1;
        __syncthreads();

#pragma unroll
        for (int k = 0; k < 16; k++) {
            float4 x0 = *reinterpret_cast<const float4*>(&As[k][ty << 3]);
            float4 x1 = *reinterpret_cast<const float4*>(&As[k][(ty << 3) + 4]);
            float4 y  = *reinterpret_cast<const float4*>(&Bs[k][tx << 2]);
            float xr[8] = {x0.x, x0.y, x0.z, x0.w, x1.x, x1.y, x1.z, x1.w};
            float yr[4] = {y.x, y.y, y.z, y.w};
#pragma unroll
            for (int i = 0; i < 8; i++)
#pragma unroll
                for (int j = 0; j < 4; j++)
                    acc[i][j] = fmaf(xr[i], yr[j], acc[i][j]);
        }
        __syncthreads();
    }

#pragma unroll
    for (int i = 0; i < 8; i++) {
        float4 o;
        o.x = acc[i][0]; o.y = acc[i][1]; o.z = acc[i][2]; o.w = acc[i][3];
        size_t rowg = (size_t)(b * QQ) + row0 + (ty << 3) + i;
        *reinterpret_cast<float4*>(
            &g_comb[rowg * DC + DQS + col0 + (tx << 2)]) = o;
    }
}

// ---------------------------------------------------------------------------
// Launch
// ---------------------------------------------------------------------------
extern "C" void kernel_launch(void* const* d_in, const int* in_sizes, int n_in,
                              void* d_out, int out_size)
{
    const float* query  = (const float*)d_in[0];
    const float* memory = (const float*)d_in[1];
    const unsigned int* mask = (const unsigned int*)d_in[2];
    const float* Wk = (const float*)d_in[3];
    const float* bk = (const float*)d_in[4];
    const float* Wq = (const float*)d_in[5];
    const float* bq = (const float*)d_in[6];
    const float* Wl = (const float*)d_in[7];
    const float* bl = (const float*)d_in[8];
    const float* Wo = (const float*)d_in[9];
    const float* bo = (const float*)d_in[10];

    float* out     = (float*)d_out;              // [B,Q,QS]
    float* weights = out + BB * QQ * DQS;        // [B,Q,M]

    float *qprojPtr, *kprojPtr, *combPtr;
    cudaGetSymbolAddress((void**)&qprojPtr, g_qproj);
    cudaGetSymbolAddress((void**)&kprojPtr, g_kproj);
    cudaGetSymbolAddress((void**)&combPtr, g_comb);

    // 1) query -> comb[:, :512]  (independent of everything else)
    copy_query_kernel<<<512, 256>>>(query);

    // 2) projections
    gemm_nt<<<dim3(HH / 64, BB * QQ / 64), 128>>>(
        query, DQS, Wq, DQS, bq, qprojPtr, HH, DQS, 0);
    gemm_nt<<<dim3(HH / 64, BB * MMM / 64), 128>>>(
        memory, DKS, Wk, DKS, bk, kprojPtr, HH, DKS, 0);

    // 3) fused additive scores + softmax -> weights (second output region)
    scores_kernel<<<BB * QQ / 4, 128>>>(Wl, bl, mask, weights);

    // 4) attns = weights @ memory -> comb[:, 512:]
    attn_gemm<<<dim3(DKS / 64, QQ / 64, BB), 128>>>(weights, memory);

    // 5) output = tanh(comb @ Wo^T + bo)
    gemm_nt<<<dim3(DQS / 64, BB * QQ / 64), 128>>>(
        combPtr, DC, Wo, DC, bo, out, DQS, DC, 1);
}

// round 4
// speedup vs baseline: 1.4784x; 1.4784x over previous
#include <cuda_runtime.h>

#define BB 4
#define QQ 256
#define MMM 256
#define HH 512
#define DQS 512
#define DKS 512
#define DC (DQS + DKS)

// Scratch device globals
__device__ float g_qproj[BB * QQ * HH];    // 2 MB
__device__ float g_kproj[BB * MMM * HH];   // 2 MB
__device__ float g_logits[BB * QQ * MMM];  // 1 MB
__device__ float g_partial[BB * QQ * DQS]; // 2 MB  query @ Wo1^T + bo
__device__ float g_attns[BB * QQ * DKS];   // 2 MB

// ---------------------------------------------------------------------------
// NT GEMM body: C[r][n] = act(sum_k A[r*lda+k]*W[n*ldw+k] [+bias] [+P]) .
// 256 threads. BM = MI*16 rows x 64 cols. micro-tile MI x 4.
// ---------------------------------------------------------------------------
template<int MI, bool BIAS, bool TANH, bool ADDP>
__device__ __forceinline__ void gemm_nt_body(
    int tile, int nColTiles,
    const float* __restrict__ A, int lda,
    const float* __restrict__ W, int ldw,
    const float* __restrict__ bias,
    const float* __restrict__ P, int ldp,
    float* __restrict__ C, int ldc, int K)
{
    constexpr int BM = MI * 16;
    constexpr int NA = BM / 64;   // A float4-chunks per thread (2 for BM=128, 1 for 64)
    __shared__ float As[16][BM];
    __shared__ float Ws[16][64];

    const int tid = threadIdx.x;
    const int tx = tid & 15;
    const int ty = tid >> 4;
    const int row0 = (tile / nColTiles) * BM;
    const int col0 = (tile % nColTiles) * 64;

    int ar[NA], akq[NA];
#pragma unroll
    for (int c = 0; c < NA; c++) {
        int idx = tid + c * 256;
        ar[c] = idx >> 2;
        akq[c] = (idx & 3) << 2;
    }
    const int wr = tid >> 2, wkq = (tid & 3) << 2;

    float acc[MI][4];
#pragma unroll
    for (int i = 0; i < MI; i++)
#pragma unroll
        for (int j = 0; j < 4; j++) acc[i][j] = 0.f;

    float4 pa[NA], pw;
#pragma unroll
    for (int c = 0; c < NA; c++)
        pa[c] = *reinterpret_cast<const float4*>(A + (size_t)(row0 + ar[c]) * lda + akq[c]);
    pw = *reinterpret_cast<const float4*>(W + (size_t)(col0 + wr) * ldw + wkq);

    for (int k0 = 0; k0 < K; k0 += 16) {
#pragma unroll
        for (int c = 0; c < NA; c++) {
            As[akq[c] + 0][ar[c]] = pa[c].x;
            As[akq[c] + 1][ar[c]] = pa[c].y;
            As[akq[c] + 2][ar[c]] = pa[c].z;
            As[akq[c] + 3][ar[c]] = pa[c].w;
        }
        Ws[wkq + 0][wr] = pw.x; Ws[wkq + 1][wr] = pw.y;
        Ws[wkq + 2][wr] = pw.z; Ws[wkq + 3][wr] = pw.w;
        __syncthreads();

        int kn = k0 + 16;
        if (kn < K) {
#pragma unroll
            for (int c = 0; c < NA; c++)
                pa[c] = *reinterpret_cast<const float4*>(
                    A + (size_t)(row0 + ar[c]) * lda + kn + akq[c]);
            pw = *reinterpret_cast<const float4*>(
                W + (size_t)(col0 + wr) * ldw + kn + wkq);
        }

#pragma unroll
        for (int k = 0; k < 16; k++) {
            float a[MI];
#pragma unroll
            for (int v = 0; v < MI; v += 4) {
                float4 t = *reinterpret_cast<const float4*>(&As[k][ty * MI + v]);
                a[v + 0] = t.x; a[v + 1] = t.y; a[v + 2] = t.z; a[v + 3] = t.w;
            }
            float4 wv = *reinterpret_cast<const float4*>(&Ws[k][tx << 2]);
            float w4[4] = {wv.x, wv.y, wv.z, wv.w};
#pragma unroll
            for (int i = 0; i < MI; i++)
#pragma unroll
                for (int j = 0; j < 4; j++)
                    acc[i][j] = fmaf(a[i], w4[j], acc[i][j]);
        }
        __syncthreads();
    }

    float bv[4] = {0.f, 0.f, 0.f, 0.f};
    if (BIAS) {
#pragma unroll
        for (int j = 0; j < 4; j++) bv[j] = bias[col0 + (tx << 2) + j];
    }

#pragma unroll
    for (int i = 0; i < MI; i++) {
        int row = row0 + ty * MI + i;
        float4 o;
        float* op = &o.x;
#pragma unroll
        for (int j = 0; j < 4; j++) op[j] = acc[i][j] + bv[j];
        if (ADDP) {
            float4 p = *reinterpret_cast<const float4*>(
                P + (size_t)row * ldp + col0 + (tx << 2));
            o.x += p.x; o.y += p.y; o.z += p.z; o.w += p.w;
        }
        if (TANH) {
            o.x = tanhf(o.x); o.y = tanhf(o.y);
            o.z = tanhf(o.z); o.w = tanhf(o.w);
        }
        *reinterpret_cast<float4*>(
            C + (size_t)row * ldc + col0 + (tx << 2)) = o;
    }
}

// ---------------------------------------------------------------------------
// K1: both projections in one launch. 128 tiles of 128x64, 256 threads.
// tiles 0..63: qproj (query x Wq -> g_qproj); 64..127: kproj.
// ---------------------------------------------------------------------------
__global__ void __launch_bounds__(256) k1_proj(
    const float* __restrict__ query, const float* __restrict__ memory,
    const float* __restrict__ Wq, const float* __restrict__ bq,
    const float* __restrict__ Wk, const float* __restrict__ bk)
{
    int t = blockIdx.x;
    if (t < 64)
        gemm_nt_body<8, true, false, false>(t, 8, query, DQS, Wq, DQS, bq,
                                            nullptr, 0, g_qproj, HH, DQS);
    else
        gemm_nt_body<8, true, false, false>(t - 64, 8, memory, DKS, Wk, DKS, bk,
                                            nullptr, 0, g_kproj, HH, DKS);
}

// ---------------------------------------------------------------------------
// Scores body: 256 threads = 8 warps, warp w owns q-row q0+w, computes 64 m.
// Writes raw logits (no bias needed: uniform shift cancels in softmax).
// ---------------------------------------------------------------------------
__device__ __forceinline__ void scores_body(int bid, const float* __restrict__ Wl)
{
    // bid in [0, 512): b = bid>>7, qg = (bid>>2)&31, mg = bid&3
    const int b  = bid >> 7;
    const int qg = (bid >> 2) & 31;
    const int mg = bid & 3;
    const int q0 = qg << 3;
    const int m0base = mg << 6;

    __shared__ float ks[16][512];   // 32 KB

    const int tid = threadIdx.x;
    const int lane = tid & 31;
    const int w = tid >> 5;
    const int q = q0 + w;

    float qr[16], wl[16];
    const float* qp = g_qproj + ((size_t)(b * QQ + q)) * HH;
#pragma unroll
    for (int j = 0; j < 16; j++) {
        qr[j] = qp[lane + 32 * j];
        wl[j] = Wl[lane + 32 * j];
    }

    float* lout = g_logits + ((size_t)(b * QQ + q)) * MMM;

    for (int t = 0; t < 4; t++) {
        const int m0 = m0base + (t << 4);
        __syncthreads();
        const float* kp = g_kproj + ((size_t)(b * MMM + m0)) * HH;
#pragma unroll
        for (int i = 0; i < 8; i++) {
            int idx = tid + (i << 8);
            int mm = idx >> 7;
            int c4 = (idx & 127) << 2;
            *reinterpret_cast<float4*>(&ks[mm][c4]) =
                *reinterpret_cast<const float4*>(kp + mm * HH + c4);
        }
        __syncthreads();

#pragma unroll 4
        for (int mm = 0; mm < 16; mm++) {
            float acc = 0.f;
#pragma unroll
            for (int j = 0; j < 16; j++) {
                float s = qr[j] + ks[mm][lane + 32 * j];
                float th;
                asm("tanh.approx.f32 %0, %1;" : "=f"(th) : "f"(s));
                acc = fmaf(wl[j], th, acc);
            }
#pragma unroll
            for (int o = 16; o > 0; o >>= 1)
                acc += __shfl_xor_sync(0xFFFFFFFFu, acc, o);
            if (lane == 0) lout[m0 + mm] = acc;
        }
    }
}

// ---------------------------------------------------------------------------
// K2: fused scores (512 blocks) + query@Wo1^T GEMM (64 blocks).
// The GEMM blocks ride the idle FMA pipe while scores saturate MUFU.
// ---------------------------------------------------------------------------
__global__ void __launch_bounds__(256) k2_scores_qwo1(
    const float* __restrict__ query,
    const float* __restrict__ Wo, const float* __restrict__ bo,
    const float* __restrict__ Wl)
{
    if (blockIdx.x < 64)
        gemm_nt_body<8, true, false, false>(blockIdx.x, 8, query, DQS, Wo, DC, bo,
                                            nullptr, 0, g_partial, DQS, DQS);
    else
        scores_body(blockIdx.x - 64, Wl);
}

// ---------------------------------------------------------------------------
// K3: softmax. 256 blocks x 128 threads, warp per q-row.
// ---------------------------------------------------------------------------
__global__ void __launch_bounds__(128) k3_softmax(
    const unsigned int* __restrict__ mask,
    float* __restrict__ weights)
{
    const int bid = blockIdx.x;
    const int b = bid >> 6;
    const int lane = threadIdx.x & 31;
    const int w = threadIdx.x >> 5;
    const int q = ((bid & 63) << 2) + w;

    const float* lin = g_logits + ((size_t)(b * QQ + q)) * MMM;
    const unsigned int* mrow = mask + b * MMM;

    float v[8];
    float mx = -3.4e38f;
#pragma unroll
    for (int j = 0; j < 8; j++) {
        int m = lane + 32 * j;
        float s = lin[m];
        if (mrow[m] != 0u) s = -1e18f;
        v[j] = s;
        mx = fmaxf(mx, s);
    }
#pragma unroll
    for (int o = 16; o > 0; o >>= 1)
        mx = fmaxf(mx, __shfl_xor_sync(0xFFFFFFFFu, mx, o));
    float sum = 0.f;
#pragma unroll
    for (int j = 0; j < 8; j++) {
        v[j] = __expf(v[j] - mx);
        sum += v[j];
    }
#pragma unroll
    for (int o = 16; o > 0; o >>= 1)
        sum += __shfl_xor_sync(0xFFFFFFFFu, sum, o);
    float inv = 1.f / sum;

    float* wout = weights + ((size_t)(b * QQ + q)) * MMM;
#pragma unroll
    for (int j = 0; j < 8; j++)
        wout[lane + 32 * j] = v[j] * inv;
}

// ---------------------------------------------------------------------------
// K4: attns = weights @ memory (NN). 64x64 tile, 256 threads, 4x4 micro.
// grid = 4(qtiles) * 8(dtiles) * 4(b) = 128 blocks.
// ---------------------------------------------------------------------------
__global__ void __launch_bounds__(256) k4_attn(
    const float* __restrict__ Wt, const float* __restrict__ mem)
{
    const int bid = blockIdx.x;
    const int b = bid >> 5;
    const int qt = (bid >> 3) & 3;
    const int dt = bid & 7;

    const float* A = Wt + (size_t)b * QQ * MMM;
    const float* Bm = mem + (size_t)b * MMM * DKS;

    __shared__ float As[16][64];
    __shared__ float Bs[16][64];

    const int tid = threadIdx.x;
    const int tx = tid & 15;
    const int ty = tid >> 4;
    const int row0 = qt << 6;
    const int col0 = dt << 6;

    const int ar = tid >> 2, akq = (tid & 3) << 2;
    const int bk = tid >> 4, bn = (tid & 15) << 2;

    float acc[4][4];
#pragma unroll
    for (int i = 0; i < 4; i++)
#pragma unroll
        for (int j = 0; j < 4; j++) acc[i][j] = 0.f;

    float4 pa = *reinterpret_cast<const float4*>(A + (size_t)(row0 + ar) * MMM + akq);
    float4 pb = *reinterpret_cast<const float4*>(Bm + (size_t)bk * DKS + col0 + bn);

    for (int k0 = 0; k0 < MMM; k0 += 16) {
        As[akq + 0][ar] = pa.x; As[akq + 1][ar] = pa.y;
        As[akq + 2][ar] = pa.z; As[akq + 3][ar] = pa.w;
        *reinterpret_cast<float4*>(&Bs[bk][bn]) = pb;
        __syncthreads();

        int kn = k0 + 16;
        if (kn < MMM) {
            pa = *reinterpret_cast<const float4*>(A + (size_t)(row0 + ar) * MMM + kn + akq);
            pb = *reinterpret_cast<const float4*>(Bm + (size_t)(kn + bk) * DKS + col0 + bn);
        }

#pragma unroll
        for (int k = 0; k < 16; k++) {
            float4 av = *reinterpret_cast<const float4*>(&As[k][ty << 2]);
            float4 bv = *reinterpret_cast<const float4*>(&Bs[k][tx << 2]);
            float a4[4] = {av.x, av.y, av.z, av.w};
            float b4[4] = {bv.x, bv.y, bv.z, bv.w};
#pragma unroll
            for (int i = 0; i < 4; i++)
#pragma unroll
                for (int j = 0; j < 4; j++)
                    acc[i][j] = fmaf(a4[i], b4[j], acc[i][j]);
        }
        __syncthreads();
    }

#pragma unroll
    for (int i = 0; i < 4; i++) {
        float4 o;
        o.x = acc[i][0]; o.y = acc[i][1]; o.z = acc[i][2]; o.w = acc[i][3];
        size_t row = (size_t)b * QQ + row0 + (ty << 2) + i;
        *reinterpret_cast<float4*>(&g_attns[row * DKS + col0 + (tx << 2)]) = o;
    }
}

// ---------------------------------------------------------------------------
// K5: output = tanh(g_partial + attns @ Wo2^T). 64x64 tiles, 128 blocks.
// ---------------------------------------------------------------------------
__global__ void __launch_bounds__(256) k5_outfinal(
    const float* __restrict__ Wo, float* __restrict__ out)
{
    gemm_nt_body<4, false, true, true>(blockIdx.x, 8,
        g_attns, DKS, Wo + DQS, DC, nullptr,
        g_partial, DQS, out, DQS, DKS);
}

// ---------------------------------------------------------------------------
// Launch
// ---------------------------------------------------------------------------
extern "C" void kernel_launch(void* const* d_in, const int* in_sizes, int n_in,
                              void* d_out, int out_size)
{
    const float* query  = (const float*)d_in[0];
    const float* memory = (const float*)d_in[1];
    const unsigned int* mask = (const unsigned int*)d_in[2];
    const float* Wk = (const float*)d_in[3];
    const float* bk = (const float*)d_in[4];
    const float* Wq = (const float*)d_in[5];
    const float* bq = (const float*)d_in[6];
    const float* Wl = (const float*)d_in[7];
    // d_in[8] = bl (uniform shift — cancels in softmax)
    const float* Wo = (const float*)d_in[9];
    const float* bo = (const float*)d_in[10];

    float* out     = (float*)d_out;
    float* weights = out + BB * QQ * DQS;

    k1_proj<<<128, 256>>>(query, memory, Wq, bq, Wk, bk);
    k2_scores_qwo1<<<576, 256>>>(query, Wo, bo, Wl);
    k3_softmax<<<256, 128>>>(mask, weights);
    k4_attn<<<128, 256>>>(weights, memory);
    k5_outfinal<<<128, 256>>>(Wo, out);
}

// round 5
// speedup vs baseline: 2.1832x; 1.4767x over previous
#include <cuda_runtime.h>
#include <stdint.h>

#define BB 4
#define QQ 256
#define MMM 256
#define HH 512
#define DQS 512
#define DKS 512
#define DC (DQS + DKS)

// Scratch device globals
__device__ float g_qproj[BB * QQ * HH];    // 2 MB
__device__ float g_kproj[BB * MMM * HH];   // 2 MB
__device__ float g_logits[BB * QQ * MMM];  // 1 MB
__device__ float g_partial[BB * QQ * DQS]; // 2 MB  query @ Wo1^T + bo
__device__ float g_attns[BB * QQ * DKS];   // 2 MB

// ---------------------------------------------------------------------------
// tf32 helpers
// ---------------------------------------------------------------------------
__device__ __forceinline__ float f2tf32(float x) {
    uint32_t r;
    asm("cvt.rna.tf32.f32 %0, %1;" : "=r"(r) : "f"(x));
    return __uint_as_float(r);
}
__device__ __forceinline__ uint32_t fu(float x) { return __float_as_uint(x); }

__device__ __forceinline__ void mma_tf32(float c[4], const uint32_t a[4],
                                         const uint32_t b[2]) {
    asm volatile(
        "mma.sync.aligned.m16n8k8.row.col.f32.tf32.tf32.f32 "
        "{%0,%1,%2,%3}, {%4,%5,%6,%7}, {%8,%9}, {%0,%1,%2,%3};"
        : "+f"(c[0]), "+f"(c[1]), "+f"(c[2]), "+f"(c[3])
        : "r"(a[0]), "r"(a[1]), "r"(a[2]), "r"(a[3]), "r"(b[0]), "r"(b[1]));
}

// ---------------------------------------------------------------------------
// NT tf32 GEMM body: C[r][n] = act(sum_k A[r,k]*W[n,k] [+bias[n]] [+P[r,n]])
// Block 64x64, K-step 32, 128 threads = 4 warps (2x2), warp tile 32x32.
// Smem stride 36 -> fragment LDS conflict-free.
// ---------------------------------------------------------------------------
template<bool BIAS, bool ADDP, bool TANH>
__device__ __forceinline__ void gemm_nt_tf32(
    int row0, int col0,
    const float* __restrict__ A, int lda,
    const float* __restrict__ W, int ldw,
    const float* __restrict__ bias,
    const float* __restrict__ P, int ldp,
    float* __restrict__ C, int ldc, int K)
{
    __shared__ float As[64][36];
    __shared__ float Ws[64][36];

    const int tid  = threadIdx.x;
    const int lane = tid & 31;
    const int g    = lane >> 2;
    const int tg   = lane & 3;
    const int w    = tid >> 5;
    const int wm   = (w >> 1) << 5;
    const int wn   = (w & 1) << 5;

    // loaders: 64 rows x 8 float4 = 512 f4 per tile, 4 per thread
    int lr[4], lc[4];
#pragma unroll
    for (int c = 0; c < 4; c++) {
        int idx = tid + (c << 7);
        lr[c] = idx >> 3;
        lc[c] = (idx & 7) << 2;
    }

    float acc[2][4][4];
#pragma unroll
    for (int mi = 0; mi < 2; mi++)
#pragma unroll
        for (int ni = 0; ni < 4; ni++)
#pragma unroll
            for (int j = 0; j < 4; j++) acc[mi][ni][j] = 0.f;

    float4 pa[4], pw[4];
#pragma unroll
    for (int c = 0; c < 4; c++) {
        pa[c] = *reinterpret_cast<const float4*>(A + (size_t)(row0 + lr[c]) * lda + lc[c]);
        pw[c] = *reinterpret_cast<const float4*>(W + (size_t)(col0 + lr[c]) * ldw + lc[c]);
    }

    for (int k0 = 0; k0 < K; k0 += 32) {
#pragma unroll
        for (int c = 0; c < 4; c++) {
            float4 va = pa[c], vw = pw[c];
            float4 ca = make_float4(f2tf32(va.x), f2tf32(va.y), f2tf32(va.z), f2tf32(va.w));
            float4 cw = make_float4(f2tf32(vw.x), f2tf32(vw.y), f2tf32(vw.z), f2tf32(vw.w));
            *reinterpret_cast<float4*>(&As[lr[c]][lc[c]]) = ca;
            *reinterpret_cast<float4*>(&Ws[lr[c]][lc[c]]) = cw;
        }
        __syncthreads();

        int kn = k0 + 32;
        if (kn < K) {
#pragma unroll
            for (int c = 0; c < 4; c++) {
                pa[c] = *reinterpret_cast<const float4*>(
                    A + (size_t)(row0 + lr[c]) * lda + kn + lc[c]);
                pw[c] = *reinterpret_cast<const float4*>(
                    W + (size_t)(col0 + lr[c]) * ldw + kn + lc[c]);
            }
        }

#pragma unroll
        for (int ks = 0; ks < 4; ks++) {
            const int kk = ks << 3;
            uint32_t af[2][4], bf[4][2];
#pragma unroll
            for (int mi = 0; mi < 2; mi++) {
                int r = wm + (mi << 4) + g;
                af[mi][0] = fu(As[r][kk + tg]);
                af[mi][1] = fu(As[r + 8][kk + tg]);
                af[mi][2] = fu(As[r][kk + tg + 4]);
                af[mi][3] = fu(As[r + 8][kk + tg + 4]);
            }
#pragma unroll
            for (int ni = 0; ni < 4; ni++) {
                int cn = wn + (ni << 3) + g;
                bf[ni][0] = fu(Ws[cn][kk + tg]);
                bf[ni][1] = fu(Ws[cn][kk + tg + 4]);
            }
#pragma unroll
            for (int mi = 0; mi < 2; mi++)
#pragma unroll
                for (int ni = 0; ni < 4; ni++)
                    mma_tf32(acc[mi][ni], af[mi], bf[ni]);
        }
        __syncthreads();
    }

    // epilogue
#pragma unroll
    for (int mi = 0; mi < 2; mi++) {
#pragma unroll
        for (int ni = 0; ni < 4; ni++) {
            int col = col0 + wn + (ni << 3) + (tg << 1);
            float b0 = 0.f, b1 = 0.f;
            if (BIAS) { b0 = bias[col]; b1 = bias[col + 1]; }
            int r0 = row0 + wm + (mi << 4) + g;
            int r1 = r0 + 8;
            float v0 = acc[mi][ni][0] + b0;
            float v1 = acc[mi][ni][1] + b1;
            float v2 = acc[mi][ni][2] + b0;
            float v3 = acc[mi][ni][3] + b1;
            if (ADDP) {
                float2 p0 = *reinterpret_cast<const float2*>(P + (size_t)r0 * ldp + col);
                float2 p1 = *reinterpret_cast<const float2*>(P + (size_t)r1 * ldp + col);
                v0 += p0.x; v1 += p0.y; v2 += p1.x; v3 += p1.y;
            }
            if (TANH) {
                v0 = tanhf(v0); v1 = tanhf(v1); v2 = tanhf(v2); v3 = tanhf(v3);
            }
            *reinterpret_cast<float2*>(C + (size_t)r0 * ldc + col) = make_float2(v0, v1);
            *reinterpret_cast<float2*>(C + (size_t)r1 * ldc + col) = make_float2(v2, v3);
        }
    }
}

// ---------------------------------------------------------------------------
// K1: three NT GEMMs in one launch (384 blocks of 128 thr):
//  gemmid 0: qproj = query @ Wq^T + bq
//  gemmid 1: kproj = memory @ Wk^T + bk
//  gemmid 2: partial = query @ Wo1^T + bo
// ---------------------------------------------------------------------------
__global__ void __launch_bounds__(128) k1_proj(
    const float* __restrict__ query, const float* __restrict__ memory,
    const float* __restrict__ Wq, const float* __restrict__ bq,
    const float* __restrict__ Wk, const float* __restrict__ bk,
    const float* __restrict__ Wo, const float* __restrict__ bo)
{
    const int gemmid = blockIdx.x >> 7;
    const int tile = blockIdx.x & 127;
    const int row0 = (tile >> 3) << 6;
    const int col0 = (tile & 7) << 6;
    if (gemmid == 0)
        gemm_nt_tf32<true, false, false>(row0, col0, query, DQS, Wq, DQS, bq,
                                         nullptr, 0, g_qproj, HH, DQS);
    else if (gemmid == 1)
        gemm_nt_tf32<true, false, false>(row0, col0, memory, DKS, Wk, DKS, bk,
                                         nullptr, 0, g_kproj, HH, DKS);
    else
        gemm_nt_tf32<true, false, false>(row0, col0, query, DQS, Wo, DC, bo,
                                         nullptr, 0, g_partial, DQS, DQS);
}

// ---------------------------------------------------------------------------
// K2: scores (MUFU-bound). 512 blocks x 256 thr = 8 warps.
// Warp w owns q-row; block covers 8 q-rows x 64 m-cols.
// ---------------------------------------------------------------------------
__global__ void __launch_bounds__(256) k2_scores(const float* __restrict__ Wl)
{
    const int bid = blockIdx.x;
    const int b  = bid >> 7;
    const int qg = (bid >> 2) & 31;
    const int mg = bid & 3;
    const int q0 = qg << 3;
    const int m0base = mg << 6;

    __shared__ float ks[16][512];   // 32 KB

    const int tid = threadIdx.x;
    const int lane = tid & 31;
    const int w = tid >> 5;
    const int q = q0 + w;

    float qr[16], wl[16];
    const float* qp = g_qproj + ((size_t)(b * QQ + q)) * HH;
#pragma unroll
    for (int j = 0; j < 16; j++) {
        qr[j] = qp[lane + 32 * j];
        wl[j] = Wl[lane + 32 * j];
    }

    float* lout = g_logits + ((size_t)(b * QQ + q)) * MMM;

    for (int t = 0; t < 4; t++) {
        const int m0 = m0base + (t << 4);
        __syncthreads();
        const float* kp = g_kproj + ((size_t)(b * MMM + m0)) * HH;
#pragma unroll
        for (int i = 0; i < 8; i++) {
            int idx = tid + (i << 8);
            int mm = idx >> 7;
            int c4 = (idx & 127) << 2;
            *reinterpret_cast<float4*>(&ks[mm][c4]) =
                *reinterpret_cast<const float4*>(kp + mm * HH + c4);
        }
        __syncthreads();

#pragma unroll 4
        for (int mm = 0; mm < 16; mm++) {
            float acc = 0.f;
#pragma unroll
            for (int j = 0; j < 16; j++) {
                float s = qr[j] + ks[mm][lane + 32 * j];
                float th;
                asm("tanh.approx.f32 %0, %1;" : "=f"(th) : "f"(s));
                acc = fmaf(wl[j], th, acc);
            }
#pragma unroll
            for (int o = 16; o > 0; o >>= 1)
                acc += __shfl_xor_sync(0xFFFFFFFFu, acc, o);
            if (lane == 0) lout[m0 + mm] = acc;
        }
    }
}

// ---------------------------------------------------------------------------
// K3: softmax. 256 blocks x 128 threads, warp per q-row.
// ---------------------------------------------------------------------------
__global__ void __launch_bounds__(128) k3_softmax(
    const unsigned int* __restrict__ mask,
    float* __restrict__ weights)
{
    const int bid = blockIdx.x;
    const int b = bid >> 6;
    const int lane = threadIdx.x & 31;
    const int w = threadIdx.x >> 5;
    const int q = ((bid & 63) << 2) + w;

    const float* lin = g_logits + ((size_t)(b * QQ + q)) * MMM;
    const unsigned int* mrow = mask + b * MMM;

    float v[8];
    float mx = -3.4e38f;
#pragma unroll
    for (int j = 0; j < 8; j++) {
        int m = lane + 32 * j;
        float s = lin[m];
        if (mrow[m] != 0u) s = -1e18f;
        v[j] = s;
        mx = fmaxf(mx, s);
    }
#pragma unroll
    for (int o = 16; o > 0; o >>= 1)
        mx = fmaxf(mx, __shfl_xor_sync(0xFFFFFFFFu, mx, o));
    float sum = 0.f;
#pragma unroll
    for (int j = 0; j < 8; j++) {
        v[j] = __expf(v[j] - mx);
        sum += v[j];
    }
#pragma unroll
    for (int o = 16; o > 0; o >>= 1)
        sum += __shfl_xor_sync(0xFFFFFFFFu, sum, o);
    float inv = 1.f / sum;

    float* wout = weights + ((size_t)(b * QQ + q)) * MMM;
#pragma unroll
    for (int j = 0; j < 8; j++)
        wout[lane + 32 * j] = v[j] * inv;
}

// ---------------------------------------------------------------------------
// K4: attns = weights @ memory (NN, tf32). Block 64x64, 128 thr, BK=32.
// B tile stored [k][n] with stride 72 -> conflict-free fragment LDS.
// grid = 4b * 4qt * 8dt = 128 blocks.
// ---------------------------------------------------------------------------
__global__ void __launch_bounds__(128) k4_attn(
    const float* __restrict__ Wt, const float* __restrict__ mem)
{
    const int bid = blockIdx.x;
    const int b = bid >> 5;
    const int tile = bid & 31;
    const int row0 = (tile >> 3) << 6;   // q
    const int col0 = (tile & 7) << 6;    // d

    const float* A  = Wt  + (size_t)b * QQ * MMM;   // lda = MMM
    const float* Bm = mem + (size_t)b * MMM * DKS;  // ldb = DKS

    __shared__ float As[64][36];
    __shared__ float Bs[32][72];

    const int tid  = threadIdx.x;
    const int lane = tid & 31;
    const int g    = lane >> 2;
    const int tg   = lane & 3;
    const int w    = tid >> 5;
    const int wm   = (w >> 1) << 5;
    const int wn   = (w & 1) << 5;

    int ar[4], ac[4], br[4], bc[4];
#pragma unroll
    for (int c = 0; c < 4; c++) {
        int idx = tid + (c << 7);
        ar[c] = idx >> 3;  ac[c] = (idx & 7) << 2;    // A: 64 rows x 8 f4
        br[c] = idx >> 4;  bc[c] = (idx & 15) << 2;   // B: 32 rows x 16 f4
    }

    float acc[2][4][4];
#pragma unroll
    for (int mi = 0; mi < 2; mi++)
#pragma unroll
        for (int ni = 0; ni < 4; ni++)
#pragma unroll
            for (int j = 0; j < 4; j++) acc[mi][ni][j] = 0.f;

    float4 pa[4], pb[4];
#pragma unroll
    for (int c = 0; c < 4; c++) {
        pa[c] = *reinterpret_cast<const float4*>(A + (size_t)(row0 + ar[c]) * MMM + ac[c]);
        pb[c] = *reinterpret_cast<const float4*>(Bm + (size_t)br[c] * DKS + col0 + bc[c]);
    }

    for (int k0 = 0; k0 < MMM; k0 += 32) {
#pragma unroll
        for (int c = 0; c < 4; c++) {
            float4 va = pa[c], vb = pb[c];
            *reinterpret_cast<float4*>(&As[ar[c]][ac[c]]) =
                make_float4(f2tf32(va.x), f2tf32(va.y), f2tf32(va.z), f2tf32(va.w));
            *reinterpret_cast<float4*>(&Bs[br[c]][bc[c]]) =
                make_float4(f2tf32(vb.x), f2tf32(vb.y), f2tf32(vb.z), f2tf32(vb.w));
        }
        __syncthreads();

        int kn = k0 + 32;
        if (kn < MMM) {
#pragma unroll
            for (int c = 0; c < 4; c++) {
                pa[c] = *reinterpret_cast<const float4*>(
                    A + (size_t)(row0 + ar[c]) * MMM + kn + ac[c]);
                pb[c] = *reinterpret_cast<const float4*>(
                    Bm + (size_t)(kn + br[c]) * DKS + col0 + bc[c]);
            }
        }

#pragma unroll
        for (int ks = 0; ks < 4; ks++) {
            const int kk = ks << 3;
            uint32_t af[2][4], bf[4][2];
#pragma unroll
            for (int mi = 0; mi < 2; mi++) {
                int r = wm + (mi << 4) + g;
                af[mi][0] = fu(As[r][kk + tg]);
                af[mi][1] = fu(As[r + 8][kk + tg]);
                af[mi][2] = fu(As[r][kk + tg + 4]);
                af[mi][3] = fu(As[r + 8][kk + tg + 4]);
            }
#pragma unroll
            for (int ni = 0; ni < 4; ni++) {
                int cn = wn + (ni << 3) + g;
                bf[ni][0] = fu(Bs[kk + tg][cn]);
                bf[ni][1] = fu(Bs[kk + tg + 4][cn]);
            }
#pragma unroll
            for (int mi = 0; mi < 2; mi++)
#pragma unroll
                for (int ni = 0; ni < 4; ni++)
                    mma_tf32(acc[mi][ni], af[mi], bf[ni]);
        }
        __syncthreads();
    }

#pragma unroll
    for (int mi = 0; mi < 2; mi++) {
#pragma unroll
        for (int ni = 0; ni < 4; ni++) {
            int col = col0 + wn + (ni << 3) + (tg << 1);
            size_t r0 = (size_t)b * QQ + row0 + wm + (mi << 4) + g;
            size_t r1 = r0 + 8;
            *reinterpret_cast<float2*>(&g_attns[r0 * DKS + col]) =
                make_float2(acc[mi][ni][0], acc[mi][ni][1]);
            *reinterpret_cast<float2*>(&g_attns[r1 * DKS + col]) =
                make_float2(acc[mi][ni][2], acc[mi][ni][3]);
        }
    }
}

// ---------------------------------------------------------------------------
// K5: output = tanh(partial + attns @ Wo2^T). 128 blocks of 64x64.
// ---------------------------------------------------------------------------
__global__ void __launch_bounds__(128) k5_out(
    const float* __restrict__ Wo, float* __restrict__ out)
{
    const int tile = blockIdx.x;
    const int row0 = (tile >> 3) << 6;
    const int col0 = (tile & 7) << 6;
    gemm_nt_tf32<false, true, true>(row0, col0, g_attns, DKS, Wo + DQS, DC,
                                    nullptr, g_partial, DQS, out, DQS, DKS);
}

// ---------------------------------------------------------------------------
// Launch
// ---------------------------------------------------------------------------
extern "C" void kernel_launch(void* const* d_in, const int* in_sizes, int n_in,
                              void* d_out, int out_size)
{
    const float* query  = (const float*)d_in[0];
    const float* memory = (const float*)d_in[1];
    const unsigned int* mask = (const unsigned int*)d_in[2];
    const float* Wk = (const float*)d_in[3];
    const float* bk = (const float*)d_in[4];
    const float* Wq = (const float*)d_in[5];
    const float* bq = (const float*)d_in[6];
    const float* Wl = (const float*)d_in[7];
    // d_in[8] = bl (uniform shift — cancels in softmax)
    const float* Wo = (const float*)d_in[9];
    const float* bo = (const float*)d_in[10];

    float* out     = (float*)d_out;
    float* weights = out + BB * QQ * DQS;

    k1_proj<<<384, 128>>>(query, memory, Wq, bq, Wk, bk, Wo, bo);
    k2_scores<<<512, 256>>>(Wl);
    k3_softmax<<<256, 128>>>(mask, weights);
    k4_attn<<<128, 128>>>(weights, memory);
    k5_out<<<128, 128>>>(Wo, out);
}

// round 6
// speedup vs baseline: 2.4610x; 1.1273x over previous
#include <cuda_runtime.h>
#include <stdint.h>

#define BB 4
#define QQ 256
#define MMM 256
#define HH 512
#define DQS 512
#define DKS 512
#define DC (DQS + DKS)

// Scratch device globals
__device__ float g_qproj[BB * QQ * HH];    // 2 MB
__device__ float g_kproj[BB * MMM * HH];   // 2 MB
__device__ float g_logits[BB * QQ * MMM];  // 1 MB
__device__ float g_partial[BB * QQ * DQS]; // 2 MB  query @ Wo1^T + bo
__device__ float g_P2[BB * MMM * DQS];     // 2 MB  memory @ Wo2^T

// ---------------------------------------------------------------------------
// tf32 helpers
// ---------------------------------------------------------------------------
__device__ __forceinline__ float f2tf32(float x) {
    uint32_t r;
    asm("cvt.rna.tf32.f32 %0, %1;" : "=r"(r) : "f"(x));
    return __uint_as_float(r);
}
__device__ __forceinline__ uint32_t fu(float x) { return __float_as_uint(x); }

__device__ __forceinline__ void mma_tf32(float c[4], const uint32_t a[4],
                                         const uint32_t b[2]) {
    asm volatile(
        "mma.sync.aligned.m16n8k8.row.col.f32.tf32.tf32.f32 "
        "{%0,%1,%2,%3}, {%4,%5,%6,%7}, {%8,%9}, {%0,%1,%2,%3};"
        : "+f"(c[0]), "+f"(c[1]), "+f"(c[2]), "+f"(c[3])
        : "r"(a[0]), "r"(a[1]), "r"(a[2]), "r"(a[3]), "r"(b[0]), "r"(b[1]));
}

// ---------------------------------------------------------------------------
// NT tf32 GEMM body, 256 threads, 64x64 tile, BK=32.
// 8 warps in 2x4 grid, warp tile 32x16 (2 m-frags x 2 n-frags).
// Smem stride 36 -> all fragment LDS conflict-free.
// C[r][n] = act( sum_k A[r,k]*W[n,k] [+bias[n]] )
// ---------------------------------------------------------------------------
template<bool BIAS>
__device__ __forceinline__ void gemm_nt_256(
    float (*As)[36], float (*Ws)[36],
    int row0, int col0,
    const float* __restrict__ A, int lda,
    const float* __restrict__ W, int ldw,
    const float* __restrict__ bias,
    float* __restrict__ C, int ldc, int K)
{
    const int tid  = threadIdx.x;
    const int lane = tid & 31;
    const int g    = lane >> 2;
    const int tg   = lane & 3;
    const int w    = tid >> 5;
    const int wm   = (w >> 2) << 5;   // 0 or 32
    const int wn   = (w & 3) << 4;    // 0,16,32,48

    // loaders: A/W tiles are 64 rows x 8 float4; 2 f4 per thread each
    int lr[2], lc[2];
#pragma unroll
    for (int c = 0; c < 2; c++) {
        int idx = tid + (c << 8);
        lr[c] = idx >> 3;
        lc[c] = (idx & 7) << 2;
    }

    float acc[2][2][4];
#pragma unroll
    for (int mi = 0; mi < 2; mi++)
#pragma unroll
        for (int ni = 0; ni < 2; ni++)
#pragma unroll
            for (int j = 0; j < 4; j++) acc[mi][ni][j] = 0.f;

    float4 pa[2], pw[2];
#pragma unroll
    for (int c = 0; c < 2; c++) {
        pa[c] = *reinterpret_cast<const float4*>(A + (size_t)(row0 + lr[c]) * lda + lc[c]);
        pw[c] = *reinterpret_cast<const float4*>(W + (size_t)(col0 + lr[c]) * ldw + lc[c]);
    }

    for (int k0 = 0; k0 < K; k0 += 32) {
#pragma unroll
        for (int c = 0; c < 2; c++) {
            float4 va = pa[c], vw = pw[c];
            *reinterpret_cast<float4*>(&As[lr[c]][lc[c]]) =
                make_float4(f2tf32(va.x), f2tf32(va.y), f2tf32(va.z), f2tf32(va.w));
            *reinterpret_cast<float4*>(&Ws[lr[c]][lc[c]]) =
                make_float4(f2tf32(vw.x), f2tf32(vw.y), f2tf32(vw.z), f2tf32(vw.w));
        }
        __syncthreads();

        int kn = k0 + 32;
        if (kn < K) {
#pragma unroll
            for (int c = 0; c < 2; c++) {
                pa[c] = *reinterpret_cast<const float4*>(
                    A + (size_t)(row0 + lr[c]) * lda + kn + lc[c]);
                pw[c] = *reinterpret_cast<const float4*>(
                    W + (size_t)(col0 + lr[c]) * ldw + kn + lc[c]);
            }
        }

#pragma unroll
        for (int ks = 0; ks < 4; ks++) {
            const int kk = ks << 3;
            uint32_t af[2][4], bf[2][2];
#pragma unroll
            for (int mi = 0; mi < 2; mi++) {
                int r = wm + (mi << 4) + g;
                af[mi][0] = fu(As[r][kk + tg]);
                af[mi][1] = fu(As[r + 8][kk + tg]);
                af[mi][2] = fu(As[r][kk + tg + 4]);
                af[mi][3] = fu(As[r + 8][kk + tg + 4]);
            }
#pragma unroll
            for (int ni = 0; ni < 2; ni++) {
                int cn = wn + (ni << 3) + g;
                bf[ni][0] = fu(Ws[cn][kk + tg]);
                bf[ni][1] = fu(Ws[cn][kk + tg + 4]);
            }
#pragma unroll
            for (int mi = 0; mi < 2; mi++)
#pragma unroll
                for (int ni = 0; ni < 2; ni++)
                    mma_tf32(acc[mi][ni], af[mi], bf[ni]);
        }
        __syncthreads();
    }

#pragma unroll
    for (int mi = 0; mi < 2; mi++) {
#pragma unroll
        for (int ni = 0; ni < 2; ni++) {
            int col = col0 + wn + (ni << 3) + (tg << 1);
            float b0 = 0.f, b1 = 0.f;
            if (BIAS) { b0 = bias[col]; b1 = bias[col + 1]; }
            int r0 = row0 + wm + (mi << 4) + g;
            int r1 = r0 + 8;
            *reinterpret_cast<float2*>(C + (size_t)r0 * ldc + col) =
                make_float2(acc[mi][ni][0] + b0, acc[mi][ni][1] + b1);
            *reinterpret_cast<float2*>(C + (size_t)r1 * ldc + col) =
                make_float2(acc[mi][ni][2] + b0, acc[mi][ni][3] + b1);
        }
    }
}

// ---------------------------------------------------------------------------
// K1: qproj + kproj. 256 blocks x 256 thr; 128 tiles each GEMM.
// ---------------------------------------------------------------------------
__global__ void __launch_bounds__(256) k1_proj(
    const float* __restrict__ query, const float* __restrict__ memory,
    const float* __restrict__ Wq, const float* __restrict__ bq,
    const float* __restrict__ Wk, const float* __restrict__ bk)
{
    __shared__ float As[64][36];
    __shared__ float Ws[64][36];
    const int t = blockIdx.x & 127;
    const int row0 = (t >> 3) << 6;
    const int col0 = (t & 7) << 6;
    if (blockIdx.x < 128)
        gemm_nt_256<true>(As, Ws, row0, col0, query, DQS, Wq, DQS, bq,
                          g_qproj, HH, DQS);
    else
        gemm_nt_256<true>(As, Ws, row0, col0, memory, DKS, Wk, DKS, bk,
                          g_kproj, HH, DKS);
}

// ---------------------------------------------------------------------------
// Scores body (MUFU-bound). 256 thr = 8 warps; warp owns one q-row,
// block covers 8 q-rows x 64 m.
// ---------------------------------------------------------------------------
__device__ __forceinline__ void scores_body(int bid, float (*ks)[512],
                                            const float* __restrict__ Wl)
{
    const int b  = bid >> 7;
    const int qg = (bid >> 2) & 31;
    const int mg = bid & 3;
    const int q0 = qg << 3;
    const int m0base = mg << 6;

    const int tid = threadIdx.x;
    const int lane = tid & 31;
    const int w = tid >> 5;
    const int q = q0 + w;

    float qr[16], wl[16];
    const float* qp = g_qproj + ((size_t)(b * QQ + q)) * HH;
#pragma unroll
    for (int j = 0; j < 16; j++) {
        qr[j] = qp[lane + 32 * j];
        wl[j] = Wl[lane + 32 * j];
    }

    float* lout = g_logits + ((size_t)(b * QQ + q)) * MMM;

    for (int t = 0; t < 4; t++) {
        const int m0 = m0base + (t << 4);
        __syncthreads();
        const float* kp = g_kproj + ((size_t)(b * MMM + m0)) * HH;
#pragma unroll
        for (int i = 0; i < 8; i++) {
            int idx = tid + (i << 8);
            int mm = idx >> 7;
            int c4 = (idx & 127) << 2;
            *reinterpret_cast<float4*>(&ks[mm][c4]) =
                *reinterpret_cast<const float4*>(kp + mm * HH + c4);
        }
        __syncthreads();

#pragma unroll 4
        for (int mm = 0; mm < 16; mm++) {
            float acc = 0.f;
#pragma unroll
            for (int j = 0; j < 16; j++) {
                float s = qr[j] + ks[mm][lane + 32 * j];
                float th;
                asm("tanh.approx.f32 %0, %1;" : "=f"(th) : "f"(s));
                acc = fmaf(wl[j], th, acc);
            }
#pragma unroll
            for (int o = 16; o > 0; o >>= 1)
                acc += __shfl_xor_sync(0xFFFFFFFFu, acc, o);
            if (lane == 0) lout[m0 + mm] = acc;
        }
    }
}

// ---------------------------------------------------------------------------
// K2: scores (512 blocks) + partial = query@Wo1^T + bo (128) +
//     P2 = memory@Wo2^T (128). GEMMs ride the tensor pipe under the
//     MUFU-bound scores blocks. Smem union keeps 32 KB/block.
// ---------------------------------------------------------------------------
__global__ void __launch_bounds__(256) k2_scores_fused(
    const float* __restrict__ query, const float* __restrict__ memory,
    const float* __restrict__ Wo, const float* __restrict__ bo,
    const float* __restrict__ Wl)
{
    __shared__ __align__(16) union {
        float ks[16][512];                         // 32 KB (scores)
        struct { float As[64][36]; float Ws[64][36]; } g;  // 18 KB (gemm)
    } sm;

    const int bid = blockIdx.x;
    if (bid < 512) {
        scores_body(bid, sm.ks, Wl);
    } else if (bid < 640) {
        const int t = bid - 512;
        const int row0 = (t >> 3) << 6;
        const int col0 = (t & 7) << 6;
        gemm_nt_256<true>(sm.g.As, sm.g.Ws, row0, col0,
                          query, DQS, Wo, DC, bo, g_partial, DQS, DQS);
    } else {
        const int t = bid - 640;
        const int row0 = (t >> 3) << 6;
        const int col0 = (t & 7) << 6;
        gemm_nt_256<false>(sm.g.As, sm.g.Ws, row0, col0,
                           memory, DKS, Wo + DQS, DC, nullptr, g_P2, DQS, DKS);
    }
}

// ---------------------------------------------------------------------------
// K3: softmax. 256 blocks x 128 threads, warp per q-row.
// ---------------------------------------------------------------------------
__global__ void __launch_bounds__(128) k3_softmax(
    const unsigned int* __restrict__ mask,
    float* __restrict__ weights)
{
    const int bid = blockIdx.x;
    const int b = bid >> 6;
    const int lane = threadIdx.x & 31;
    const int w = threadIdx.x >> 5;
    const int q = ((bid & 63) << 2) + w;

    const float* lin = g_logits + ((size_t)(b * QQ + q)) * MMM;
    const unsigned int* mrow = mask + b * MMM;

    float v[8];
    float mx = -3.4e38f;
#pragma unroll
    for (int j = 0; j < 8; j++) {
        int m = lane + 32 * j;
        float s = lin[m];
        if (mrow[m] != 0u) s = -1e18f;
        v[j] = s;
        mx = fmaxf(mx, s);
    }
#pragma unroll
    for (int o = 16; o > 0; o >>= 1)
        mx = fmaxf(mx, __shfl_xor_sync(0xFFFFFFFFu, mx, o));
    float sum = 0.f;
#pragma unroll
    for (int j = 0; j < 8; j++) {
        v[j] = __expf(v[j] - mx);
        sum += v[j];
    }
#pragma unroll
    for (int o = 16; o > 0; o >>= 1)
        sum += __shfl_xor_sync(0xFFFFFFFFu, sum, o);
    float inv = 1.f / sum;

    float* wout = weights + ((size_t)(b * QQ + q)) * MMM;
#pragma unroll
    for (int j = 0; j < 8; j++)
        wout[lane + 32 * j] = v[j] * inv;
}

// ---------------------------------------------------------------------------
// K4f: out = tanh(partial + weights @ P2)  (batched NN, K = M = 256).
// 256 thr, 64x64 tile; B tile stored [k][n] stride 72 (conflict-free).
// grid = 4b x 4 qtiles x 8 otiles = 128 blocks.
// ---------------------------------------------------------------------------
__global__ void __launch_bounds__(256) k4_final(
    const float* __restrict__ Wt, float* __restrict__ out)
{
    const int bid = blockIdx.x;
    const int b = bid >> 5;
    const int tile = bid & 31;
    const int row0 = (tile >> 3) << 6;   // q within batch
    const int col0 = (tile & 7) << 6;    // o

    const float* A  = Wt   + (size_t)b * QQ * MMM;   // weights, lda = MMM
    const float* Bm = g_P2 + (size_t)b * MMM * DQS;  // P2, ldb = DQS

    __shared__ float As[64][36];
    __shared__ float Bs[32][72];

    const int tid  = threadIdx.x;
    const int lane = tid & 31;
    const int g    = lane >> 2;
    const int tg   = lane & 3;
    const int w    = tid >> 5;
    const int wm   = (w >> 2) << 5;
    const int wn   = (w & 3) << 4;

    int ar[2], ac[2], br[2], bc[2];
#pragma unroll
    for (int c = 0; c < 2; c++) {
        int idx = tid + (c << 8);
        ar[c] = idx >> 3;  ac[c] = (idx & 7) << 2;    // A: 64 x 8 f4
        br[c] = idx >> 4;  bc[c] = (idx & 15) << 2;   // B: 32 x 16 f4
    }

    float acc[2][2][4];
#pragma unroll
    for (int mi = 0; mi < 2; mi++)
#pragma unroll
        for (int ni = 0; ni < 2; ni++)
#pragma unroll
            for (int j = 0; j < 4; j++) acc[mi][ni][j] = 0.f;

    float4 pa[2], pb[2];
#pragma unroll
    for (int c = 0; c < 2; c++) {
        pa[c] = *reinterpret_cast<const float4*>(A + (size_t)(row0 + ar[c]) * MMM + ac[c]);
        pb[c] = *reinterpret_cast<const float4*>(Bm + (size_t)br[c] * DQS + col0 + bc[c]);
    }

    for (int k0 = 0; k0 < MMM; k0 += 32) {
#pragma unroll
        for (int c = 0; c < 2; c++) {
            float4 va = pa[c], vb = pb[c];
            *reinterpret_cast<float4*>(&As[ar[c]][ac[c]]) =
                make_float4(f2tf32(va.x), f2tf32(va.y), f2tf32(va.z), f2tf32(va.w));
            *reinterpret_cast<float4*>(&Bs[br[c]][bc[c]]) =
                make_float4(f2tf32(vb.x), f2tf32(vb.y), f2tf32(vb.z), f2tf32(vb.w));
        }
        __syncthreads();

        int kn = k0 + 32;
        if (kn < MMM) {
#pragma unroll
            for (int c = 0; c < 2; c++) {
                pa[c] = *reinterpret_cast<const float4*>(
                    A + (size_t)(row0 + ar[c]) * MMM + kn + ac[c]);
                pb[c] = *reinterpret_cast<const float4*>(
                    Bm + (size_t)(kn + br[c]) * DQS + col0 + bc[c]);
            }
        }

#pragma unroll
        for (int ks = 0; ks < 4; ks++) {
            const int kk = ks << 3;
            uint32_t af[2][4], bf[2][2];
#pragma unroll
            for (int mi = 0; mi < 2; mi++) {
                int r = wm + (mi << 4) + g;
                af[mi][0] = fu(As[r][kk + tg]);
                af[mi][1] = fu(As[r + 8][kk + tg]);
                af[mi][2] = fu(As[r][kk + tg + 4]);
                af[mi][3] = fu(As[r + 8][kk + tg + 4]);
            }
#pragma unroll
            for (int ni = 0; ni < 2; ni++) {
                int cn = wn + (ni << 3) + g;
                bf[ni][0] = fu(Bs[kk + tg][cn]);
                bf[ni][1] = fu(Bs[kk + tg + 4][cn]);
            }
#pragma unroll
            for (int mi = 0; mi < 2; mi++)
#pragma unroll
                for (int ni = 0; ni < 2; ni++)
                    mma_tf32(acc[mi][ni], af[mi], bf[ni]);
        }
        __syncthreads();
    }

#pragma unroll
    for (int mi = 0; mi < 2; mi++) {
#pragma unroll
        for (int ni = 0; ni < 2; ni++) {
            int col = col0 + wn + (ni << 3) + (tg << 1);
            size_t r0 = (size_t)b * QQ + row0 + wm + (mi << 4) + g;
            size_t r1 = r0 + 8;
            float2 p0 = *reinterpret_cast<const float2*>(&g_partial[r0 * DQS + col]);
            float2 p1 = *reinterpret_cast<const float2*>(&g_partial[r1 * DQS + col]);
            *reinterpret_cast<float2*>(out + r0 * DQS + col) =
                make_float2(tanhf(acc[mi][ni][0] + p0.x), tanhf(acc[mi][ni][1] + p0.y));
            *reinterpret_cast<float2*>(out + r1 * DQS + col) =
                make_float2(tanhf(acc[mi][ni][2] + p1.x), tanhf(acc[mi][ni][3] + p1.y));
        }
    }
}

// ---------------------------------------------------------------------------
// Launch
// ---------------------------------------------------------------------------
extern "C" void kernel_launch(void* const* d_in, const int* in_sizes, int n_in,
                              void* d_out, int out_size)
{
    const float* query  = (const float*)d_in[0];
    const float* memory = (const float*)d_in[1];
    const unsigned int* mask = (const unsigned int*)d_in[2];
    const float* Wk = (const float*)d_in[3];
    const float* bk = (const float*)d_in[4];
    const float* Wq = (const float*)d_in[5];
    const float* bq = (const float*)d_in[6];
    const float* Wl = (const float*)d_in[7];
    // d_in[8] = bl (uniform shift — cancels in softmax)
    const float* Wo = (const float*)d_in[9];
    const float* bo = (const float*)d_in[10];

    float* out     = (float*)d_out;
    float* weights = out + BB * QQ * DQS;

    k1_proj<<<256, 256>>>(query, memory, Wq, bq, Wk, bk);
    k2_scores_fused<<<768, 256>>>(query, memory, Wo, bo, Wl);
    k3_softmax<<<256, 128>>>(mask, weights);
    k4_final<<<128, 256>>>(weights, out);
}